// round 3
// baseline (speedup 1.0000x reference)
#include <cuda_runtime.h>
#include <cstdint>

// Problem constants (fixed by the dataset)
#define MAXN      100000
#define F_IN      256
#define HC        128       // H*C = 2*64
#define NEG_SLOPE 0.2f

// Scratch: xl||xr per node, [N][256] (first 128 = xl, last 128 = xr)
__device__ float g_xlxr[(size_t)MAXN * 256];
// Unnormalized softmax denominator per (node, head)
__device__ float g_denom[(size_t)MAXN * 2];

// ---------------------------------------------------------------------------
// K0: zero the output accumulator and the denominators
// ---------------------------------------------------------------------------
__global__ void zero_kernel(float* __restrict__ out, int n_out, int n_den) {
    int i = blockIdx.x * blockDim.x + threadIdx.x;
    if (i < n_out) out[i] = 0.0f;
    if (i < n_den) g_denom[i] = 0.0f;
}

// ---------------------------------------------------------------------------
// K1: tf32 tensor-core projection GEMM.
//   blockIdx.y == 0 : xl = x @ Wl^T + bl -> g_xlxr[:, 0:128]
//   blockIdx.y == 1 : xr = x @ Wr^T + br -> g_xlxr[:, 128:256]
// 128x128 block tile, BK=16 double-buffered, 8 warps (4 M x 2 N),
// warp tile 32x64 via mma.sync.m16n8k8 tf32 (2 x 8 mma tiles).
//
// Smem k-permute: within each 8-wide k group, column k is stored at
// k' = 2*(k&3) + ((k>>2)&1). This makes each thread's two tf32 fragment
// elements (k, k+4) adjacent -> LDS.64 fragment loads.
// ---------------------------------------------------------------------------
__device__ __forceinline__ unsigned f2tf32(float f) {
    unsigned u;
    asm("cvt.rna.tf32.f32 %0, %1;" : "=r"(u) : "f"(f));
    return u;
}

__global__ __launch_bounds__(256) void gemm_tf32_kernel(
    const float* __restrict__ x,
    const float* __restrict__ Wl, const float* __restrict__ bl,
    const float* __restrict__ Wr, const float* __restrict__ br,
    int nrows)
{
    __shared__ unsigned sA[2][128][18];
    __shared__ unsigned sB[2][128][18];

    const float* __restrict__ W  = blockIdx.y ? Wr : Wl;
    const float* __restrict__ bv = blockIdx.y ? br : bl;

    const int tid  = threadIdx.x;
    const int lane = tid & 31;
    const int wid  = tid >> 5;
    const int wm   = (wid & 3) * 32;   // warp row offset in block tile
    const int wn   = (wid >> 2) * 64;  // warp col offset in block tile
    const int rowBase = blockIdx.x * 128;

    // Loader: thread -> one row (0..127), 8 consecutive k (two float4)
    const int lr = tid >> 1;
    const int lc = (tid & 1) * 8;      // 0 or 8 (also = group*8 in permuted layout)

    const int qid = lane >> 2;         // 0..7
    const int rid = lane & 3;          // 0..3

    float acc[2][8][4];
#pragma unroll
    for (int mt = 0; mt < 2; mt++)
#pragma unroll
        for (int nt = 0; nt < 8; nt++)
#pragma unroll
            for (int i = 0; i < 4; i++) acc[mt][nt][i] = 0.0f;

    float4 va0, va1, vb0, vb1;

    // ---- tile loaders ------------------------------------------------------
    auto load_tile = [&](int kt) {
        const int gr = rowBase + lr;
        if (gr < nrows) {
            const float* ap = x + (size_t)gr * F_IN + kt * 16 + lc;
            va0 = *reinterpret_cast<const float4*>(ap);
            va1 = *reinterpret_cast<const float4*>(ap + 4);
        } else {
            va0 = va1 = make_float4(0.f, 0.f, 0.f, 0.f);
        }
        const float* bp = W + (size_t)lr * F_IN + kt * 16 + lc;
        vb0 = *reinterpret_cast<const float4*>(bp);
        vb1 = *reinterpret_cast<const float4*>(bp + 4);
    };

    auto sts_tile = [&](int b) {
        unsigned* pa = &sA[b][lr][lc];
        pa[0] = f2tf32(va0.x); pa[2] = f2tf32(va0.y);
        pa[4] = f2tf32(va0.z); pa[6] = f2tf32(va0.w);
        pa[1] = f2tf32(va1.x); pa[3] = f2tf32(va1.y);
        pa[5] = f2tf32(va1.z); pa[7] = f2tf32(va1.w);
        unsigned* pb = &sB[b][lr][lc];
        pb[0] = f2tf32(vb0.x); pb[2] = f2tf32(vb0.y);
        pb[4] = f2tf32(vb0.z); pb[6] = f2tf32(vb0.w);
        pb[1] = f2tf32(vb1.x); pb[3] = f2tf32(vb1.y);
        pb[5] = f2tf32(vb1.z); pb[7] = f2tf32(vb1.w);
    };

    auto compute = [&](int b) {
#pragma unroll
        for (int s = 0; s < 2; s++) {
            const int kc = s * 8 + 2 * rid;
            unsigned af[2][4];
#pragma unroll
            for (int mt = 0; mt < 2; mt++) {
                const int r = wm + mt * 16 + qid;
                uint2 t0 = *reinterpret_cast<const uint2*>(&sA[b][r][kc]);
                uint2 t1 = *reinterpret_cast<const uint2*>(&sA[b][r + 8][kc]);
                af[mt][0] = t0.x; af[mt][1] = t1.x;
                af[mt][2] = t0.y; af[mt][3] = t1.y;
            }
            unsigned bf[8][2];
#pragma unroll
            for (int nt = 0; nt < 8; nt++) {
                const int cn = wn + nt * 8 + qid;
                uint2 t = *reinterpret_cast<const uint2*>(&sB[b][cn][kc]);
                bf[nt][0] = t.x; bf[nt][1] = t.y;
            }
#pragma unroll
            for (int mt = 0; mt < 2; mt++)
#pragma unroll
                for (int nt = 0; nt < 8; nt++) {
                    asm volatile(
                        "mma.sync.aligned.m16n8k8.row.col.f32.tf32.tf32.f32 "
                        "{%0,%1,%2,%3}, {%4,%5,%6,%7}, {%8,%9}, {%0,%1,%2,%3};"
                        : "+f"(acc[mt][nt][0]), "+f"(acc[mt][nt][1]),
                          "+f"(acc[mt][nt][2]), "+f"(acc[mt][nt][3])
                        : "r"(af[mt][0]), "r"(af[mt][1]),
                          "r"(af[mt][2]), "r"(af[mt][3]),
                          "r"(bf[nt][0]), "r"(bf[nt][1]));
                }
        }
    };

    // ---- pipelined main loop ----------------------------------------------
    load_tile(0);
    sts_tile(0);
    __syncthreads();
#pragma unroll 4
    for (int kt = 0; kt < 16; kt++) {
        if (kt < 15) load_tile(kt + 1);
        compute(kt & 1);
        if (kt < 15) sts_tile((kt + 1) & 1);
        __syncthreads();
    }

    // ---- epilogue: bias + store into combined scratch ---------------------
    const int colBase = blockIdx.y * HC;
#pragma unroll
    for (int mt = 0; mt < 2; mt++) {
#pragma unroll
        for (int half = 0; half < 2; half++) {
            const int row = rowBase + wm + mt * 16 + qid + half * 8;
            if (row >= nrows) continue;
            float* dst = g_xlxr + (size_t)row * 256 + colBase;
#pragma unroll
            for (int nt = 0; nt < 8; nt++) {
                const int col = wn + nt * 8 + 2 * rid;
                float2 o;
                o.x = acc[mt][nt][half * 2 + 0] + bv[col];
                o.y = acc[mt][nt][half * 2 + 1] + bv[col + 1];
                *reinterpret_cast<float2*>(dst + col) = o;
            }
        }
    }
}

// ---------------------------------------------------------------------------
// K2: one warp per edge (including self-loops). Softmax shift is skipped
// (mathematically invariant; logits are O(10) so exp is safe in fp32).
// Accumulates UNNORMALIZED p * xl[src] into out, and p into g_denom.
// ---------------------------------------------------------------------------
__global__ __launch_bounds__(256) void edge_kernel(
    const int* __restrict__ ei,     // [2, E] row-major
    const float* __restrict__ att,  // [2, 64] -> linear 128
    float* __restrict__ out,        // [N, 128] accumulator
    int E, int Etot)
{
    const int warp = (blockIdx.x * blockDim.x + threadIdx.x) >> 5;
    if (warp >= Etot) return;
    const int lane = threadIdx.x & 31;

    int src, dst;
    if (warp < E) {
        src = ei[warp];
        dst = ei[E + warp];
    } else {
        src = dst = warp - E;   // self loop
    }

    const int c4 = lane * 4;   // channel offset in [0,128); lanes 0-15 head0, 16-31 head1

    const float4 xl = *reinterpret_cast<const float4*>(g_xlxr + (size_t)src * 256 + c4);
    const float4 xr = *reinterpret_cast<const float4*>(g_xlxr + (size_t)dst * 256 + HC + c4);
    const float4 a  = *reinterpret_cast<const float4*>(att + c4);

    float sx = xl.x + xr.x; sx = sx > 0.f ? sx : NEG_SLOPE * sx;
    float sy = xl.y + xr.y; sy = sy > 0.f ? sy : NEG_SLOPE * sy;
    float sz = xl.z + xr.z; sz = sz > 0.f ? sz : NEG_SLOPE * sz;
    float sw = xl.w + xr.w; sw = sw > 0.f ? sw : NEG_SLOPE * sw;

    float partial = a.x * sx + a.y * sy + a.z * sz + a.w * sw;
    // Reduce over the 16 lanes of this head
#pragma unroll
    for (int off = 8; off > 0; off >>= 1)
        partial += __shfl_xor_sync(0xffffffffu, partial, off);

    const float p = __expf(partial);

    if ((lane & 15) == 0)
        atomicAdd(&g_denom[(size_t)dst * 2 + (lane >> 4)], p);

    // Vector reduction (4 channels at once) into the output accumulator
    float* dptr = out + (size_t)dst * HC + c4;
    asm volatile("red.global.add.v4.f32 [%0], {%1,%2,%3,%4};"
                 :: "l"(dptr), "f"(p * xl.x), "f"(p * xl.y),
                    "f"(p * xl.z), "f"(p * xl.w)
                 : "memory");
}

// ---------------------------------------------------------------------------
// K3: normalize and add final bias (in place on d_out)
// ---------------------------------------------------------------------------
__global__ void finalize_kernel(float* __restrict__ out,
                                const float* __restrict__ bias, int n) {
    int i = blockIdx.x * blockDim.x + threadIdx.x;   // over n*128 elements
    if (i >= n * HC) return;
    int node = i >> 7;
    int j = i & 127;
    int h = j >> 6;
    out[i] = out[i] / g_denom[(size_t)node * 2 + h] + bias[j];
}

// ---------------------------------------------------------------------------
extern "C" void kernel_launch(void* const* d_in, const int* in_sizes, int n_in,
                              void* d_out, int out_size)
{
    const float* x    = (const float*)d_in[0];
    const float* Wl   = (const float*)d_in[1];
    const float* bl   = (const float*)d_in[2];
    const float* Wr   = (const float*)d_in[3];
    const float* br   = (const float*)d_in[4];
    const float* att  = (const float*)d_in[5];
    const float* bias = (const float*)d_in[6];
    const int*   ei   = (const int*)d_in[7];
    float* out = (float*)d_out;

    const int n    = in_sizes[0] / F_IN;     // 100000
    const int E    = in_sizes[7] / 2;        // 1600000
    const int Etot = E + n;

    // K0: zero accumulators
    {
        int n_out = n * HC;
        int threads = 256;
        int blocks = (n_out + threads - 1) / threads;
        zero_kernel<<<blocks, threads>>>(out, n_out, n * 2);
    }

    // K1: projection GEMM (xl and xr) on tensor cores (tf32)
    {
        dim3 grid((n + 127) / 128, 2);
        gemm_tf32_kernel<<<grid, 256>>>(x, Wl, bl, Wr, br, n);
    }

    // K2: edge pass (1 warp / edge)
    {
        int warpsPerBlock = 8;                    // 256 threads
        int blocks = (Etot + warpsPerBlock - 1) / warpsPerBlock;
        edge_kernel<<<blocks, 256>>>(ei, att, out, E, Etot);
    }

    // K3: normalize + bias
    {
        int total = n * HC;
        int threads = 256;
        int blocks = (total + threads - 1) / threads;
        finalize_kernel<<<blocks, threads>>>(out, bias, n);
    }
}

// round 4
// speedup vs baseline: 1.2200x; 1.2200x over previous
#include <cuda_runtime.h>
#include <cuda_fp16.h>
#include <cstdint>

// Problem constants (fixed by the dataset)
#define MAXN      100000
#define F_IN      256
#define HC        128       // H*C = 2*64
#define NEG_SLOPE 0.2f

// Projected features in fp16: xl (source path) and xr (target path), [N][128]
__device__ __half g_xl_h[(size_t)MAXN * HC];
__device__ __half g_xr_h[(size_t)MAXN * HC];
// Unnormalized softmax denominator per (node, head)
__device__ float g_denom[(size_t)MAXN * 2];

// ---------------------------------------------------------------------------
// K0: zero the output accumulator (float4-vectorized) and the denominators
// ---------------------------------------------------------------------------
__global__ void zero_kernel(float4* __restrict__ out4, int n4, int n_den) {
    int i = blockIdx.x * blockDim.x + threadIdx.x;
    if (i < n4) out4[i] = make_float4(0.f, 0.f, 0.f, 0.f);
    if (i < n_den) g_denom[i] = 0.0f;
}

// ---------------------------------------------------------------------------
// K1: tf32 tensor-core projection GEMM -> fp16 outputs.
//   blockIdx.y == 0 : xl = x @ Wl^T + bl -> g_xl_h
//   blockIdx.y == 1 : xr = x @ Wr^T + br -> g_xr_h
// 128x128 block tile, BK=16 double-buffered, 8 warps (4 M x 2 N),
// warp tile 32x64 via mma.sync.m16n8k8 tf32.
// Smem k-permute: k' = 2*(k&3) + ((k>>2)&1) within each 8-k group so each
// thread's tf32 fragment pair (k, k+4) is adjacent -> LDS.64 loads.
// ---------------------------------------------------------------------------
__device__ __forceinline__ unsigned f2tf32(float f) {
    unsigned u;
    asm("cvt.rna.tf32.f32 %0, %1;" : "=r"(u) : "f"(f));
    return u;
}

__global__ __launch_bounds__(256) void gemm_tf32_kernel(
    const float* __restrict__ x,
    const float* __restrict__ Wl, const float* __restrict__ bl,
    const float* __restrict__ Wr, const float* __restrict__ br,
    int nrows)
{
    __shared__ unsigned sA[2][128][18];
    __shared__ unsigned sB[2][128][18];

    const float* __restrict__ W  = blockIdx.y ? Wr : Wl;
    const float* __restrict__ bv = blockIdx.y ? br : bl;
    __half* __restrict__ outH    = blockIdx.y ? g_xr_h : g_xl_h;

    const int tid  = threadIdx.x;
    const int lane = tid & 31;
    const int wid  = tid >> 5;
    const int wm   = (wid & 3) * 32;   // warp row offset in block tile
    const int wn   = (wid >> 2) * 64;  // warp col offset in block tile
    const int rowBase = blockIdx.x * 128;

    // Loader: thread -> one row (0..127), 8 consecutive k (two float4)
    const int lr = tid >> 1;
    const int lc = (tid & 1) * 8;

    const int qid = lane >> 2;         // 0..7
    const int rid = lane & 3;          // 0..3

    float acc[2][8][4];
#pragma unroll
    for (int mt = 0; mt < 2; mt++)
#pragma unroll
        for (int nt = 0; nt < 8; nt++)
#pragma unroll
            for (int i = 0; i < 4; i++) acc[mt][nt][i] = 0.0f;

    float4 va0, va1, vb0, vb1;

    auto load_tile = [&](int kt) {
        const int gr = rowBase + lr;
        if (gr < nrows) {
            const float* ap = x + (size_t)gr * F_IN + kt * 16 + lc;
            va0 = *reinterpret_cast<const float4*>(ap);
            va1 = *reinterpret_cast<const float4*>(ap + 4);
        } else {
            va0 = va1 = make_float4(0.f, 0.f, 0.f, 0.f);
        }
        const float* bp = W + (size_t)lr * F_IN + kt * 16 + lc;
        vb0 = *reinterpret_cast<const float4*>(bp);
        vb1 = *reinterpret_cast<const float4*>(bp + 4);
    };

    auto sts_tile = [&](int b) {
        unsigned* pa = &sA[b][lr][lc];
        pa[0] = f2tf32(va0.x); pa[2] = f2tf32(va0.y);
        pa[4] = f2tf32(va0.z); pa[6] = f2tf32(va0.w);
        pa[1] = f2tf32(va1.x); pa[3] = f2tf32(va1.y);
        pa[5] = f2tf32(va1.z); pa[7] = f2tf32(va1.w);
        unsigned* pb = &sB[b][lr][lc];
        pb[0] = f2tf32(vb0.x); pb[2] = f2tf32(vb0.y);
        pb[4] = f2tf32(vb0.z); pb[6] = f2tf32(vb0.w);
        pb[1] = f2tf32(vb1.x); pb[3] = f2tf32(vb1.y);
        pb[5] = f2tf32(vb1.z); pb[7] = f2tf32(vb1.w);
    };

    auto compute = [&](int b) {
#pragma unroll
        for (int s = 0; s < 2; s++) {
            const int kc = s * 8 + 2 * rid;
            unsigned af[2][4];
#pragma unroll
            for (int mt = 0; mt < 2; mt++) {
                const int r = wm + mt * 16 + qid;
                uint2 t0 = *reinterpret_cast<const uint2*>(&sA[b][r][kc]);
                uint2 t1 = *reinterpret_cast<const uint2*>(&sA[b][r + 8][kc]);
                af[mt][0] = t0.x; af[mt][1] = t1.x;
                af[mt][2] = t0.y; af[mt][3] = t1.y;
            }
            unsigned bf[8][2];
#pragma unroll
            for (int nt = 0; nt < 8; nt++) {
                const int cn = wn + nt * 8 + qid;
                uint2 t = *reinterpret_cast<const uint2*>(&sB[b][cn][kc]);
                bf[nt][0] = t.x; bf[nt][1] = t.y;
            }
#pragma unroll
            for (int mt = 0; mt < 2; mt++)
#pragma unroll
                for (int nt = 0; nt < 8; nt++) {
                    asm volatile(
                        "mma.sync.aligned.m16n8k8.row.col.f32.tf32.tf32.f32 "
                        "{%0,%1,%2,%3}, {%4,%5,%6,%7}, {%8,%9}, {%0,%1,%2,%3};"
                        : "+f"(acc[mt][nt][0]), "+f"(acc[mt][nt][1]),
                          "+f"(acc[mt][nt][2]), "+f"(acc[mt][nt][3])
                        : "r"(af[mt][0]), "r"(af[mt][1]),
                          "r"(af[mt][2]), "r"(af[mt][3]),
                          "r"(bf[nt][0]), "r"(bf[nt][1]));
                }
        }
    };

    load_tile(0);
    sts_tile(0);
    __syncthreads();
#pragma unroll 4
    for (int kt = 0; kt < 16; kt++) {
        if (kt < 15) load_tile(kt + 1);
        compute(kt & 1);
        if (kt < 15) sts_tile((kt + 1) & 1);
        __syncthreads();
    }

    // Epilogue: bias + convert to fp16, store
#pragma unroll
    for (int mt = 0; mt < 2; mt++) {
#pragma unroll
        for (int half_ = 0; half_ < 2; half_++) {
            const int row = rowBase + wm + mt * 16 + qid + half_ * 8;
            if (row >= nrows) continue;
            __half* dst = outH + (size_t)row * HC;
#pragma unroll
            for (int nt = 0; nt < 8; nt++) {
                const int col = wn + nt * 8 + 2 * rid;
                float2 o;
                o.x = acc[mt][nt][half_ * 2 + 0] + bv[col];
                o.y = acc[mt][nt][half_ * 2 + 1] + bv[col + 1];
                *reinterpret_cast<__half2*>(dst + col) = __float22half2_rn(o);
            }
        }
    }
}

// ---------------------------------------------------------------------------
// K2: one warp per edge (including self-loops). Softmax shift skipped
// (shift-invariant; logits are O(10), exp safe in fp32). fp16 gathers,
// fp32 math + fp32 RED accumulation.
// ---------------------------------------------------------------------------
__global__ __launch_bounds__(256) void edge_kernel(
    const int* __restrict__ ei,     // [2, E] row-major
    const float* __restrict__ att,  // [2, 64] -> linear 128
    float* __restrict__ out,        // [N, 128] accumulator
    int E, int Etot)
{
    const int warp = (blockIdx.x * blockDim.x + threadIdx.x) >> 5;
    if (warp >= Etot) return;
    const int lane = threadIdx.x & 31;

    int src, dst;
    if (warp < E) {
        src = ei[warp];
        dst = ei[E + warp];
    } else {
        src = dst = warp - E;   // self loop
    }

    const int c4 = lane * 4;   // channel offset; lanes 0-15 head0, 16-31 head1

    // fp16 gathers: 4 halves = 8B per lane, 256B per row per warp (coalesced)
    const uint2 xlu = *reinterpret_cast<const uint2*>(g_xl_h + (size_t)src * HC + c4);
    const uint2 xru = *reinterpret_cast<const uint2*>(g_xr_h + (size_t)dst * HC + c4);
    const float4 a  = *reinterpret_cast<const float4*>(att + c4);

    const float2 xl01 = __half22float2(*reinterpret_cast<const __half2*>(&xlu.x));
    const float2 xl23 = __half22float2(*reinterpret_cast<const __half2*>(&xlu.y));
    const float2 xr01 = __half22float2(*reinterpret_cast<const __half2*>(&xru.x));
    const float2 xr23 = __half22float2(*reinterpret_cast<const __half2*>(&xru.y));

    float sx = xl01.x + xr01.x; sx = sx > 0.f ? sx : NEG_SLOPE * sx;
    float sy = xl01.y + xr01.y; sy = sy > 0.f ? sy : NEG_SLOPE * sy;
    float sz = xl23.x + xr23.x; sz = sz > 0.f ? sz : NEG_SLOPE * sz;
    float sw = xl23.y + xr23.y; sw = sw > 0.f ? sw : NEG_SLOPE * sw;

    float partial = a.x * sx + a.y * sy + a.z * sz + a.w * sw;
#pragma unroll
    for (int off = 8; off > 0; off >>= 1)
        partial += __shfl_xor_sync(0xffffffffu, partial, off);

    const float p = __expf(partial);

    if ((lane & 15) == 0)
        atomicAdd(&g_denom[(size_t)dst * 2 + (lane >> 4)], p);

    float* dptr = out + (size_t)dst * HC + c4;
    asm volatile("red.global.add.v4.f32 [%0], {%1,%2,%3,%4};"
                 :: "l"(dptr), "f"(p * xl01.x), "f"(p * xl01.y),
                    "f"(p * xl23.x), "f"(p * xl23.y)
                 : "memory");
}

// ---------------------------------------------------------------------------
// K3: normalize and add final bias (float4-vectorized, in place on d_out)
// ---------------------------------------------------------------------------
__global__ void finalize_kernel(float4* __restrict__ out4,
                                const float4* __restrict__ bias4, int n4) {
    int i = blockIdx.x * blockDim.x + threadIdx.x;   // over n*32 float4s
    if (i >= n4) return;
    const int node = i >> 5;
    const int q = i & 31;            // float4 index within node (0..31)
    const int h = q >> 4;            // head
    const float inv = 1.0f / g_denom[(size_t)node * 2 + h];
    float4 v = out4[i];
    const float4 b = bias4[q];
    v.x = v.x * inv + b.x;
    v.y = v.y * inv + b.y;
    v.z = v.z * inv + b.z;
    v.w = v.w * inv + b.w;
    out4[i] = v;
}

// ---------------------------------------------------------------------------
extern "C" void kernel_launch(void* const* d_in, const int* in_sizes, int n_in,
                              void* d_out, int out_size)
{
    const float* x    = (const float*)d_in[0];
    const float* Wl   = (const float*)d_in[1];
    const float* bl   = (const float*)d_in[2];
    const float* Wr   = (const float*)d_in[3];
    const float* br   = (const float*)d_in[4];
    const float* att  = (const float*)d_in[5];
    const float* bias = (const float*)d_in[6];
    const int*   ei   = (const int*)d_in[7];
    float* out = (float*)d_out;

    const int n    = in_sizes[0] / F_IN;     // 100000
    const int E    = in_sizes[7] / 2;        // 1600000
    const int Etot = E + n;

    // K0: zero accumulators (vectorized)
    {
        int n4 = n * HC / 4;
        int threads = 256;
        int blocks = (n4 + threads - 1) / threads;
        zero_kernel<<<blocks, threads>>>((float4*)out, n4, n * 2);
    }

    // K1: projection GEMM (xl and xr) on tensor cores (tf32), fp16 output
    {
        dim3 grid((n + 127) / 128, 2);
        gemm_tf32_kernel<<<grid, 256>>>(x, Wl, bl, Wr, br, n);
    }

    // K2: edge pass (1 warp / edge)
    {
        int warpsPerBlock = 8;                    // 256 threads
        int blocks = (Etot + warpsPerBlock - 1) / warpsPerBlock;
        edge_kernel<<<blocks, 256>>>(ei, att, out, E, Etot);
    }

    // K3: normalize + bias (vectorized)
    {
        int n4 = n * HC / 4;
        int threads = 256;
        int blocks = (n4 + threads - 1) / threads;
        finalize_kernel<<<blocks, threads>>>((float4*)out, (const float4*)bias, n4);
    }
}